// round 8
// baseline (speedup 1.0000x reference)
#include <cuda_runtime.h>

#define BB 4
#define NT 1024
#define NA 8192
#define DD 128
#define SS 384
#define GA_TOT (BB*NA)     // 32768 atoms
#define BT_TOT (BB*NT)     // 4096 tokens
#define PAD_VALF (-1e9f)
#define QP 72              // qT staging pitch
#define WP 68              // w staging pitch (65 cols + pad)

// scratch (no allocs allowed)
__device__ float g_a2q[BT_TOT*DD];     // [B,T,128]  2 MB
__device__ float g_Wt[SS*DD];          // W_a2q transposed [s][d]

// ---------------------------------------------------------------------------
// k0: transpose W_a2q [128][384] -> g_Wt [384][128]  (blocks 0..47)
//     + init out_res[bt][k] = b_res[k]               (all 96 blocks)
// ---------------------------------------------------------------------------
__global__ void k0_prep(const float* __restrict__ W,
                        const float* __restrict__ b_res,
                        float* __restrict__ out_res)
{
    __shared__ float t[32][33];
    __shared__ float br[33];
    const int tid = threadIdx.x;
    if (tid < 33) br[tid] = b_res[tid];

    if (blockIdx.x < 48) {
        const int x  = tid & 31;
        const int y8 = tid >> 5;
        const int td = (blockIdx.x & 3)  * 32;
        const int ts = (blockIdx.x >> 2) * 32;
#pragma unroll
        for (int j = 0; j < 32; j += 8)
            t[y8 + j][x] = W[(td + y8 + j)*SS + ts + x];
        __syncthreads();
#pragma unroll
        for (int j = 0; j < 32; j += 8)
            g_Wt[(ts + y8 + j)*DD + td + x] = t[x][y8 + j];
    } else {
        __syncthreads();
    }
    for (int i = blockIdx.x*256 + tid; i < BT_TOT*33; i += 96*256)
        out_res[i] = br[i % 33];
}

// ---------------------------------------------------------------------------
// k1: a_to_q = a[4096x384] @ Wt[384x128]
// ---------------------------------------------------------------------------
__global__ void __launch_bounds__(256) k1_gemm(const float* __restrict__ a)
{
    __shared__ float a_s[16][64];
    __shared__ float w_s[64][128];

    const int tid = threadIdx.x;
    const int bt0 = blockIdx.x * 16;
    const int dq  = tid & 31;
    const int tg  = tid >> 5;

    float acc[2][4];
#pragma unroll
    for (int t = 0; t < 2; t++)
#pragma unroll
        for (int j = 0; j < 4; j++) acc[t][j] = 0.f;

    for (int sc = 0; sc < SS; sc += 64) {
        {
            int t = tid >> 4, c = tid & 15;
            *(float4*)&a_s[t][c*4] =
                *(const float4*)(a + (size_t)(bt0 + t)*SS + sc + c*4);
        }
        {
            const float4* wsrc = (const float4*)(g_Wt + sc*DD);
            float4* wdst = (float4*)w_s;
#pragma unroll
            for (int j = 0; j < 8; j++)
                wdst[tid + j*256] = wsrc[tid + j*256];
        }
        __syncthreads();

#pragma unroll
        for (int s = 0; s < 64; s += 4) {
            float4 w0 = *(float4*)&w_s[s+0][dq*4];
            float4 w1 = *(float4*)&w_s[s+1][dq*4];
            float4 w2 = *(float4*)&w_s[s+2][dq*4];
            float4 w3 = *(float4*)&w_s[s+3][dq*4];
#pragma unroll
            for (int t = 0; t < 2; t++) {
                float4 av = *(float4*)&a_s[tg*2 + t][s];
                acc[t][0] = fmaf(av.x, w0.x, fmaf(av.y, w1.x,
                            fmaf(av.z, w2.x, fmaf(av.w, w3.x, acc[t][0]))));
                acc[t][1] = fmaf(av.x, w0.y, fmaf(av.y, w1.y,
                            fmaf(av.z, w2.y, fmaf(av.w, w3.y, acc[t][1]))));
                acc[t][2] = fmaf(av.x, w0.z, fmaf(av.y, w1.z,
                            fmaf(av.z, w2.z, fmaf(av.w, w3.z, acc[t][2]))));
                acc[t][3] = fmaf(av.x, w0.w, fmaf(av.y, w1.w,
                            fmaf(av.z, w2.w, fmaf(av.w, w3.w, acc[t][3]))));
            }
        }
        __syncthreads();
    }
#pragma unroll
    for (int t = 0; t < 2; t++) {
        float4 v = make_float4(acc[t][0], acc[t][1], acc[t][2], acc[t][3]);
        *(float4*)(g_a2q + (size_t)(bt0 + tg*2 + t)*DD + dq*4) = v;
    }
}

// ---------------------------------------------------------------------------
// k2l: gather qn = q + a2q[tok]; LayerNorm + pos head -> out_r
// 32 atoms/block, 256 threads, grid 1024
// ---------------------------------------------------------------------------
__global__ void __launch_bounds__(256) k2l_ln(
                         const float* __restrict__ q,
                         const int*   __restrict__ tok,
                         const float* __restrict__ gamma,
                         const float* __restrict__ beta,
                         const float* __restrict__ W_pos,
                         float* __restrict__ out_r)
{
    __shared__ float sh_q[32][DD];
    __shared__ float sh_pos[3][DD];
    __shared__ float sh_g[DD], sh_b[DD];
    __shared__ int   sh_tok[32];

    const int tid   = threadIdx.x;
    const int atom0 = blockIdx.x * 32;
    const int b     = atom0 >> 13;

    if (tid < 32) sh_tok[tid] = tok[atom0 + tid];
    if (tid < DD) { sh_g[tid] = gamma[tid]; sh_b[tid] = beta[tid]; }
    for (int i = tid; i < 3*DD; i += 256)
        sh_pos[i >> 7][i & 127] = W_pos[i];
    __syncthreads();

    for (int i = tid; i < 32*(DD/4); i += 256) {
        int ia = i >> 5, d4 = i & 31;
        int ga = atom0 + ia;
        int t  = sh_tok[ia];
        float4 qv = ((const float4*)q)[(size_t)ga*(DD/4) + d4];
        float4 av = ((const float4*)g_a2q)[(size_t)(b*NT + t)*(DD/4) + d4];
        *(float4*)&sh_q[ia][d4*4] =
            make_float4(qv.x+av.x, qv.y+av.y, qv.z+av.z, qv.w+av.w);
    }
    __syncthreads();

    const int lane  = tid & 31;
    const int ig    = tid >> 5;
    const int ia0   = ig * 4;
    const int dbase = lane * 4;
    for (int r = 0; r < 4; r++) {
        int ia = ia0 + r;
        float4 v = *(const float4*)&sh_q[ia][dbase];
        float s = v.x + v.y + v.z + v.w;
#pragma unroll
        for (int o = 16; o > 0; o >>= 1) s += __shfl_xor_sync(0xffffffffu, s, o);
        float mu = s * (1.f/128.f);
        float d0 = v.x-mu, d1 = v.y-mu, d2 = v.z-mu, d3 = v.w-mu;
        float sq = d0*d0 + d1*d1 + d2*d2 + d3*d3;
#pragma unroll
        for (int o = 16; o > 0; o >>= 1) sq += __shfl_xor_sync(0xffffffffu, sq, o);
        float inv = rsqrtf(sq * (1.f/128.f) + 1e-5f);
        float n0 = d0*inv*sh_g[dbase+0] + sh_b[dbase+0];
        float n1 = d1*inv*sh_g[dbase+1] + sh_b[dbase+1];
        float n2 = d2*inv*sh_g[dbase+2] + sh_b[dbase+2];
        float n3 = d3*inv*sh_g[dbase+3] + sh_b[dbase+3];
        float p0 = n0*sh_pos[0][dbase+0] + n1*sh_pos[0][dbase+1]
                 + n2*sh_pos[0][dbase+2] + n3*sh_pos[0][dbase+3];
        float p1 = n0*sh_pos[1][dbase+0] + n1*sh_pos[1][dbase+1]
                 + n2*sh_pos[1][dbase+2] + n3*sh_pos[1][dbase+3];
        float p2 = n0*sh_pos[2][dbase+0] + n1*sh_pos[2][dbase+1]
                 + n2*sh_pos[2][dbase+2] + n3*sh_pos[2][dbase+3];
#pragma unroll
        for (int o = 16; o > 0; o >>= 1) {
            p0 += __shfl_xor_sync(0xffffffffu, p0, o);
            p1 += __shfl_xor_sync(0xffffffffu, p1, o);
            p2 += __shfl_xor_sync(0xffffffffu, p2, o);
        }
        if (lane == 0) {
            size_t ro = (size_t)(atom0 + ia) * 3;
            out_r[ro+0] = p0; out_r[ro+1] = p1; out_r[ro+2] = p2;
        }
    }
}

// ---------------------------------------------------------------------------
// k2h: head GEMM  logits[64 atoms x 65] = qn @ [W_atom|W_res]^T per block.
// 256 threads = (ac 0..15: 4 atoms) x (kc 0..15: 4 cols); kc==15 also col 64.
// qn gathered on the fly (q + a2q[tok]); K tiled in 4 chunks of 32, staged
// TRANSPOSED in smem for outer-product FMA (2 LDS.128 per 16 FFMA).
// Epilogue: atom cols -> PAD rows in smem -> coalesced out_at;
//           res cols  -> run-length aggregated atomicAdd into out_res.
// grid 512 blocks.
// ---------------------------------------------------------------------------
__global__ void __launch_bounds__(256) k2h_heads(
                         const float* __restrict__ q,
                         const int*   __restrict__ tok,
                         const float* __restrict__ W_atom,
                         const float* __restrict__ W_res,
                         const int*   __restrict__ allowed,
                         const float* __restrict__ b_atom,
                         float* __restrict__ out_res,
                         float* __restrict__ out_at)
{
    __shared__ float u[64*DD];         // 32 KB: staging (uQ|uW) then row buffer
    __shared__ float lg[64*34];        // res logits, pitch 34
    __shared__ int   sh_tok[64];
    __shared__ int   sh_allowed[32];

    float* uQ = u;                     // [32][QP]
    float* uW = u + 32*QP;             // [32][WP]

    const int tid   = threadIdx.x;
    const int atom0 = blockIdx.x * 64;
    const int b     = atom0 >> 13;

    if (tid < 64) sh_tok[tid] = tok[atom0 + tid];
    else if (tid < 96) sh_allowed[tid - 64] = allowed[tid - 64];
    __syncthreads();

    const int ac   = tid & 15;
    const int kc   = tid >> 4;
    const int col0 = kc * 4;

    float acc[4][4];
#pragma unroll
    for (int j = 0; j < 4; j++) {
        float bj = (col0 + j < 32) ? __ldg(&b_atom[col0 + j]) : 0.f;
#pragma unroll
        for (int i = 0; i < 4; i++) acc[i][j] = bj;
    }
    float acc64[4] = {0.f, 0.f, 0.f, 0.f};

    // staging role: atom sa = tid&63, d-group sdg = tid>>6 (8 d each)
    const int sa  = tid & 63;
    const int sdg = tid >> 6;
    const size_t qbase = (size_t)(atom0 + sa)*DD;
    const size_t abase = (size_t)(b*NT + sh_tok[sa])*DD;

    for (int ch = 0; ch < 4; ch++) {
        const int d0 = ch*32 + sdg*8;
        float4 q0 = *(const float4*)(q + qbase + d0);
        float4 q1 = *(const float4*)(q + qbase + d0 + 4);
        float4 a0 = *(const float4*)(g_a2q + abase + d0);
        float4 a1 = *(const float4*)(g_a2q + abase + d0 + 4);
        __syncthreads();   // prev chunk compute done (loads above overlap it)
        {
            const int dl = sdg*8;
            uQ[(dl+0)*QP + sa] = q0.x + a0.x;
            uQ[(dl+1)*QP + sa] = q0.y + a0.y;
            uQ[(dl+2)*QP + sa] = q0.z + a0.z;
            uQ[(dl+3)*QP + sa] = q0.w + a0.w;
            uQ[(dl+4)*QP + sa] = q1.x + a1.x;
            uQ[(dl+5)*QP + sa] = q1.y + a1.y;
            uQ[(dl+6)*QP + sa] = q1.z + a1.z;
            uQ[(dl+7)*QP + sa] = q1.w + a1.w;
        }
        for (int idx = tid; idx < 32*WP; idx += 256) {
            int d = idx / WP, cl = idx % WP;
            float v = 0.f;
            if (cl < 32)      v = W_atom[cl*DD + ch*32 + d];
            else if (cl < 65) v = W_res[(cl-32)*DD + ch*32 + d];
            uW[idx] = v;
        }
        __syncthreads();

#pragma unroll 8
        for (int d = 0; d < 32; d++) {
            float4 qv = *(const float4*)&uQ[d*QP + ac*4];
            float4 wv = *(const float4*)&uW[d*WP + col0];
            acc[0][0] = fmaf(qv.x, wv.x, acc[0][0]);
            acc[0][1] = fmaf(qv.x, wv.y, acc[0][1]);
            acc[0][2] = fmaf(qv.x, wv.z, acc[0][2]);
            acc[0][3] = fmaf(qv.x, wv.w, acc[0][3]);
            acc[1][0] = fmaf(qv.y, wv.x, acc[1][0]);
            acc[1][1] = fmaf(qv.y, wv.y, acc[1][1]);
            acc[1][2] = fmaf(qv.y, wv.z, acc[1][2]);
            acc[1][3] = fmaf(qv.y, wv.w, acc[1][3]);
            acc[2][0] = fmaf(qv.z, wv.x, acc[2][0]);
            acc[2][1] = fmaf(qv.z, wv.y, acc[2][1]);
            acc[2][2] = fmaf(qv.z, wv.z, acc[2][2]);
            acc[2][3] = fmaf(qv.z, wv.w, acc[2][3]);
            acc[3][0] = fmaf(qv.w, wv.x, acc[3][0]);
            acc[3][1] = fmaf(qv.w, wv.y, acc[3][1]);
            acc[3][2] = fmaf(qv.w, wv.z, acc[3][2]);
            acc[3][3] = fmaf(qv.w, wv.w, acc[3][3]);
            if (kc == 15) {
                float w64 = uW[d*WP + 64];
                acc64[0] = fmaf(qv.x, w64, acc64[0]);
                acc64[1] = fmaf(qv.y, w64, acc64[1]);
                acc64[2] = fmaf(qv.z, w64, acc64[2]);
                acc64[3] = fmaf(qv.w, w64, acc64[3]);
            }
        }
    }
    __syncthreads();   // compute done; u free for reuse

    // res logits -> lg
    if (kc >= 8) {
#pragma unroll
        for (int i = 0; i < 4; i++)
#pragma unroll
            for (int j = 0; j < 4; j++)
                lg[(ac*4 + i)*34 + (col0 + j - 32)] = acc[i][j];
    }
    if (kc == 15) {
#pragma unroll
        for (int i = 0; i < 4; i++)
            lg[(ac*4 + i)*34 + 32] = acc64[i];
    }

    // PAD fill rows (u)
    for (int idx = tid; idx < 64*DD; idx += 256) u[idx] = PAD_VALF;
    __syncthreads();

    // scatter atom logits
    if (kc < 8) {
#pragma unroll
        for (int i = 0; i < 4; i++)
#pragma unroll
            for (int j = 0; j < 4; j++)
                u[(ac*4 + i)*DD + sh_allowed[col0 + j]] = acc[i][j];
    }
    __syncthreads();

    // coalesced out_at write (64 rows x 128)
    for (int idx = tid; idx < 64*(DD/4); idx += 256) {
        int ia = idx >> 5, d4 = idx & 31;
        ((float4*)out_at)[(size_t)(atom0 + ia)*(DD/4) + d4] =
            ((const float4*)u)[ia*(DD/4) + d4];
    }

    // res aggregation: 4 groups of 16 atoms x 33 logits
    if (tid < 132) {
        int kk = tid % 33;
        int i0 = (tid / 33) * 16;
        int cur  = sh_tok[i0];
        float run = 0.f;
#pragma unroll
        for (int i = 0; i < 16; i++) {
            int t = sh_tok[i0 + i];
            if (t != cur) {
                atomicAdd(&out_res[(size_t)(b*NT + cur)*33 + kk], run);
                run = 0.f; cur = t;
            }
            run += lg[(i0 + i)*34 + kk];
        }
        atomicAdd(&out_res[(size_t)(b*NT + cur)*33 + kk], run);
    }
}

// ---------------------------------------------------------------------------
extern "C" void kernel_launch(void* const* d_in, const int* in_sizes, int n_in,
                              void* d_out, int out_size)
{
    const float* a      = (const float*)d_in[0];
    const float* q      = (const float*)d_in[1];
    // d_in[2] = c            (unused by reference)
    const int*   tok    = (const int*)  d_in[3];
    // d_in[4] = atom_to_token one-hot (replaced by gather via tok)
    // d_in[5] = atom_pad_mask (all ones by construction)
    const float* W_a2q  = (const float*)d_in[6];
    const float* gamma  = (const float*)d_in[7];
    const float* beta   = (const float*)d_in[8];
    const float* W_pos  = (const float*)d_in[9];
    const float* W_res  = (const float*)d_in[10];
    const float* b_res  = (const float*)d_in[11];
    const float* W_atom = (const float*)d_in[12];
    const float* b_atom = (const float*)d_in[13];
    const int*   allowed= (const int*)  d_in[14];

    float* out     = (float*)d_out;
    float* out_r   = out;                                   // [B,NA,3]
    float* out_res = out + (size_t)BB*NA*3;                 // [B,NT,33]
    float* out_at  = out_res + (size_t)BB*NT*33;            // [B,NA,128]

    k0_prep  <<<96, 256>>>(W_a2q, b_res, out_res);
    k1_gemm  <<<BT_TOT/16, 256>>>(a);
    k2l_ln   <<<GA_TOT/32, 256>>>(q, tok, gamma, beta, W_pos, out_r);
    k2h_heads<<<GA_TOT/64, 256>>>(q, tok, W_atom, W_res, allowed, b_atom,
                                  out_res, out_at);
}

// round 9
// speedup vs baseline: 1.2982x; 1.2982x over previous
#include <cuda_runtime.h>

#define BB 4
#define NT 1024
#define NA 8192
#define DD 128
#define SS 384
#define GA_TOT (BB*NA)     // 32768 atoms
#define BT_TOT (BB*NT)     // 4096 tokens
#define PAD_VALF (-1e9f)

// scratch (no allocs allowed)
__device__ float g_a2q[BT_TOT*DD];     // [B,T,128]  2 MB
__device__ float g_sfeat[BT_TOT*DD];   // [B,T,128]  2 MB
__device__ float g_Wt[SS*DD];          // W_a2q transposed [s][d]

// ---------------------------------------------------------------------------
// k0: transpose W_a2q [128][384] -> g_Wt [384][128]  +  zero g_sfeat
// grid 48 blocks x 256 threads (48 = 4 d-tiles x 12 s-tiles of 32x32)
// ---------------------------------------------------------------------------
__global__ void k0_prep(const float* __restrict__ W)
{
    const int tid = threadIdx.x;

    int gt = blockIdx.x * 256 + tid;
    for (int i = gt; i < BT_TOT*DD/4; i += 48*256)
        ((float4*)g_sfeat)[i] = make_float4(0.f, 0.f, 0.f, 0.f);

    __shared__ float t[32][33];
    const int x  = tid & 31;
    const int y8 = tid >> 5;                  // 0..7
    const int td = (blockIdx.x & 3)  * 32;    // d tile
    const int ts = (blockIdx.x >> 2) * 32;    // s tile
#pragma unroll
    for (int j = 0; j < 32; j += 8)
        t[y8 + j][x] = W[(td + y8 + j)*SS + ts + x];
    __syncthreads();
#pragma unroll
    for (int j = 0; j < 32; j += 8)
        g_Wt[(ts + y8 + j)*DD + td + x] = t[x][y8 + j];
}

// ---------------------------------------------------------------------------
// k1: a_to_q = a[4096x384] @ Wt[384x128]
// tile: 16 tokens x 128 d, 256 threads, thread = 2 tok x 4 d. grid 256.
// ---------------------------------------------------------------------------
__global__ void __launch_bounds__(256) k1_gemm(const float* __restrict__ a)
{
    __shared__ float a_s[16][64];     // 4 KB
    __shared__ float w_s[64][128];    // 32 KB

    const int tid = threadIdx.x;
    const int bt0 = blockIdx.x * 16;
    const int dq  = tid & 31;         // d-quad (d = dq*4)
    const int tg  = tid >> 5;         // 0..7 -> tokens tg*2, tg*2+1

    float acc[2][4];
#pragma unroll
    for (int t = 0; t < 2; t++)
#pragma unroll
        for (int j = 0; j < 4; j++) acc[t][j] = 0.f;

    for (int sc = 0; sc < SS; sc += 64) {
        {
            int t = tid >> 4, c = tid & 15;
            *(float4*)&a_s[t][c*4] =
                *(const float4*)(a + (size_t)(bt0 + t)*SS + sc + c*4);
        }
        {
            const float4* wsrc = (const float4*)(g_Wt + sc*DD);
            float4* wdst = (float4*)w_s;
#pragma unroll
            for (int j = 0; j < 8; j++)
                wdst[tid + j*256] = wsrc[tid + j*256];
        }
        __syncthreads();

#pragma unroll
        for (int s = 0; s < 64; s += 4) {
            float4 w0 = *(float4*)&w_s[s+0][dq*4];
            float4 w1 = *(float4*)&w_s[s+1][dq*4];
            float4 w2 = *(float4*)&w_s[s+2][dq*4];
            float4 w3 = *(float4*)&w_s[s+3][dq*4];
#pragma unroll
            for (int t = 0; t < 2; t++) {
                float4 av = *(float4*)&a_s[tg*2 + t][s];
                acc[t][0] = fmaf(av.x, w0.x, fmaf(av.y, w1.x,
                            fmaf(av.z, w2.x, fmaf(av.w, w3.x, acc[t][0]))));
                acc[t][1] = fmaf(av.x, w0.y, fmaf(av.y, w1.y,
                            fmaf(av.z, w2.y, fmaf(av.w, w3.y, acc[t][1]))));
                acc[t][2] = fmaf(av.x, w0.z, fmaf(av.y, w1.z,
                            fmaf(av.z, w2.z, fmaf(av.w, w3.z, acc[t][2]))));
                acc[t][3] = fmaf(av.x, w0.w, fmaf(av.y, w1.w,
                            fmaf(av.z, w2.w, fmaf(av.w, w3.w, acc[t][3]))));
            }
        }
        __syncthreads();
    }
#pragma unroll
    for (int t = 0; t < 2; t++) {
        float4 v = make_float4(acc[t][0], acc[t][1], acc[t][2], acc[t][3]);
        *(float4*)(g_a2q + (size_t)(bt0 + tg*2 + t)*DD + dq*4) = v;
    }
}

// ---------------------------------------------------------------------------
// k2: per-atom fused stage (32 atoms / block, 256 threads, grid 1024)
//   qn = q + a_to_q[tok]            (gather)
//   s_feat[tok] += qn               (run-length aggregated atomics)
//   atom_type: logits + PAD assembled in smem, coalesced float4 row write
//   r_update : LayerNorm(qn) @ W_pos^T
// ---------------------------------------------------------------------------
__global__ void __launch_bounds__(256) k2_atoms(
                         const float* __restrict__ q,
                         const int*   __restrict__ tok,
                         const float* __restrict__ W_atom,
                         const float* __restrict__ b_atom,
                         const int*   __restrict__ allowed,
                         const float* __restrict__ gamma,
                         const float* __restrict__ beta,
                         const float* __restrict__ W_pos,
                         float* __restrict__ out_r,
                         float* __restrict__ out_at)
{
    __shared__ float sh_q[32][DD];       // 16 KB
    __shared__ float sh_wt[DD*33];       // 16.9 KB: Wt [d*33+k]; reused as rows
    __shared__ float sh_pos[3][DD];
    __shared__ float sh_g[DD], sh_b[DD];
    __shared__ float sh_batom[32];
    __shared__ int   sh_tok[32];
    __shared__ int   sh_allowed[32];

    const int tid   = threadIdx.x;
    const int atom0 = blockIdx.x * 32;
    const int b     = atom0 >> 13;          // atom0 / 8192

    if (tid < 32) {
        sh_tok[tid]     = tok[atom0 + tid];
        sh_batom[tid]   = b_atom[tid];
        sh_allowed[tid] = allowed[tid];
    }
    if (tid < DD) { sh_g[tid] = gamma[tid]; sh_b[tid] = beta[tid]; }
    for (int i = tid; i < 32*DD; i += 256)          // W_atom is [k][d]
        sh_wt[(i & 127)*33 + (i >> 7)] = W_atom[i]; // pitch 33: conflict-free
    for (int i = tid; i < 3*DD; i += 256)
        sh_pos[i >> 7][i & 127] = W_pos[i];
    __syncthreads();

    // ---- gather (coalesced float4) ----
    for (int i = tid; i < 32*(DD/4); i += 256) {
        int ia = i >> 5, d4 = i & 31;
        int ga = atom0 + ia;
        int t  = sh_tok[ia];
        float4 qv = ((const float4*)q)[(size_t)ga*(DD/4) + d4];
        float4 av = ((const float4*)g_a2q)[(size_t)(b*NT + t)*(DD/4) + d4];
        *(float4*)&sh_q[ia][d4*4] =
            make_float4(qv.x+av.x, qv.y+av.y, qv.z+av.z, qv.w+av.w);
    }
    __syncthreads();

    // ---- scatter-add, run-length aggregated (tok sorted => ~4 runs/block) ----
    {
        int d    = tid & 127;
        int i0   = (tid >> 7) * 16;
        int cur  = sh_tok[i0];
        float run = 0.f;
#pragma unroll
        for (int i = 0; i < 16; i++) {
            int t = sh_tok[i0 + i];
            if (t != cur) {
                atomicAdd(&g_sfeat[(size_t)(b*NT + cur)*DD + d], run);
                run = 0.f; cur = t;
            }
            run += sh_q[i0 + i][d];
        }
        atomicAdd(&g_sfeat[(size_t)(b*NT + cur)*DD + d], run);
    }

    // ---- atom-type head: thread (ig,k) owns logit k for 4 atoms ----
    const int k   = tid & 31;
    const int ig  = tid >> 5;          // warp id, 0..7
    const int ia0 = ig * 4;
    float acc0 = sh_batom[k], acc1 = acc0, acc2 = acc0, acc3 = acc0;
#pragma unroll 8
    for (int d = 0; d < DD; d += 4) {
        float w0 = sh_wt[(d+0)*33 + k], w1 = sh_wt[(d+1)*33 + k];
        float w2 = sh_wt[(d+2)*33 + k], w3 = sh_wt[(d+3)*33 + k];
        float4 q0 = *(const float4*)&sh_q[ia0+0][d];
        float4 q1 = *(const float4*)&sh_q[ia0+1][d];
        float4 q2 = *(const float4*)&sh_q[ia0+2][d];
        float4 q3 = *(const float4*)&sh_q[ia0+3][d];
        acc0 += q0.x*w0 + q0.y*w1 + q0.z*w2 + q0.w*w3;
        acc1 += q1.x*w0 + q1.y*w1 + q1.z*w2 + q1.w*w3;
        acc2 += q2.x*w0 + q2.y*w1 + q2.z*w2 + q2.w*w3;
        acc3 += q3.x*w0 + q3.y*w1 + q3.z*w2 + q3.w*w3;
    }
    __syncthreads();   // head done reading sh_wt -> reuse as row buffer

    // ---- assemble atom_type rows in smem, write coalesced ----
    float* rows = sh_wt;               // 32 x 128 = 4096 floats
    for (int i = tid; i < 32*DD; i += 256) rows[i] = PAD_VALF;
    __syncthreads();
    {
        int col = sh_allowed[k];
        rows[(ia0+0)*DD + col] = acc0;
        rows[(ia0+1)*DD + col] = acc1;
        rows[(ia0+2)*DD + col] = acc2;
        rows[(ia0+3)*DD + col] = acc3;
    }
    __syncthreads();
    for (int i = tid; i < 32*(DD/4); i += 256) {
        int ia = i >> 5, d4 = i & 31;
        ((float4*)out_at)[(size_t)(atom0 + ia)*(DD/4) + d4] =
            ((const float4*)rows)[ia*(DD/4) + d4];
    }

    // ---- LayerNorm + pos head: warp ig handles atoms ia0..ia0+3 ----
    const int lane  = k;
    const int dbase = lane * 4;
    for (int r = 0; r < 4; r++) {
        int ia = ia0 + r;
        float4 v = *(const float4*)&sh_q[ia][dbase];
        float s = v.x + v.y + v.z + v.w;
#pragma unroll
        for (int o = 16; o > 0; o >>= 1) s += __shfl_xor_sync(0xffffffffu, s, o);
        float mu = s * (1.f/128.f);
        float d0 = v.x-mu, d1 = v.y-mu, d2 = v.z-mu, d3 = v.w-mu;
        float sq = d0*d0 + d1*d1 + d2*d2 + d3*d3;
#pragma unroll
        for (int o = 16; o > 0; o >>= 1) sq += __shfl_xor_sync(0xffffffffu, sq, o);
        float inv = rsqrtf(sq * (1.f/128.f) + 1e-5f);
        float n0 = d0*inv*sh_g[dbase+0] + sh_b[dbase+0];
        float n1 = d1*inv*sh_g[dbase+1] + sh_b[dbase+1];
        float n2 = d2*inv*sh_g[dbase+2] + sh_b[dbase+2];
        float n3 = d3*inv*sh_g[dbase+3] + sh_b[dbase+3];
        float p0 = n0*sh_pos[0][dbase+0] + n1*sh_pos[0][dbase+1]
                 + n2*sh_pos[0][dbase+2] + n3*sh_pos[0][dbase+3];
        float p1 = n0*sh_pos[1][dbase+0] + n1*sh_pos[1][dbase+1]
                 + n2*sh_pos[1][dbase+2] + n3*sh_pos[1][dbase+3];
        float p2 = n0*sh_pos[2][dbase+0] + n1*sh_pos[2][dbase+1]
                 + n2*sh_pos[2][dbase+2] + n3*sh_pos[2][dbase+3];
#pragma unroll
        for (int o = 16; o > 0; o >>= 1) {
            p0 += __shfl_xor_sync(0xffffffffu, p0, o);
            p1 += __shfl_xor_sync(0xffffffffu, p1, o);
            p2 += __shfl_xor_sync(0xffffffffu, p2, o);
        }
        if (lane == 0) {
            size_t ro = (size_t)(atom0 + ia) * 3;
            out_r[ro+0] = p0; out_r[ro+1] = p1; out_r[ro+2] = p2;
        }
    }
}

// ---------------------------------------------------------------------------
// k3: res_type[bt,k] = s_feat[bt,:] . W_res[k,:] + b_res[k]
// 512 blocks x 256 threads; 8 tokens/block; warp = token, lane = k.
// W_res staged TRANSPOSED at pitch 33 -> scalar LDS banks (d+k)%32,
// conflict-free. s_feat row reads are warp-broadcast.
// ---------------------------------------------------------------------------
__global__ void __launch_bounds__(256) k3_res(const float* __restrict__ W_res,
                                              const float* __restrict__ b_res,
                                              float* __restrict__ out_res)
{
    __shared__ float shW[DD*33];     // 16.9 KB: [d*33 + k]
    __shared__ float shF[8*DD];      // 4 KB

    const int tid = threadIdx.x;
    const int bt0 = blockIdx.x * 8;

    for (int i = tid; i < 33*DD; i += 256)
        shW[(i & 127)*33 + (i >> 7)] = W_res[i];   // i = k*128 + d
    {
        const float4* src = (const float4*)(g_sfeat + (size_t)bt0*DD);
        ((float4*)shF)[tid] = src[tid];            // 256 float4 = 8 rows
    }
    __syncthreads();

    const int lane = tid & 31;                     // k
    const int w    = tid >> 5;                     // token 0..7
    const float* f = &shF[w*DD];

    float acc = b_res[lane];
#pragma unroll 16
    for (int d = 0; d < DD; d += 4) {
        float f0 = f[d+0], f1 = f[d+1], f2 = f[d+2], f3 = f[d+3];
        acc = fmaf(f0, shW[(d+0)*33 + lane],
              fmaf(f1, shW[(d+1)*33 + lane],
              fmaf(f2, shW[(d+2)*33 + lane],
              fmaf(f3, shW[(d+3)*33 + lane], acc))));
    }
    out_res[(size_t)(bt0 + w)*33 + lane] = acc;

    // k = 32: warp w, lane-parallel partial dot (4 d per lane) + reduce
    {
        const int dbase = lane * 4;
        float s = f[dbase+0]*shW[(dbase+0)*33 + 32]
                + f[dbase+1]*shW[(dbase+1)*33 + 32]
                + f[dbase+2]*shW[(dbase+2)*33 + 32]
                + f[dbase+3]*shW[(dbase+3)*33 + 32];
#pragma unroll
        for (int o = 16; o > 0; o >>= 1)
            s += __shfl_xor_sync(0xffffffffu, s, o);
        if (lane == 0)
            out_res[(size_t)(bt0 + w)*33 + 32] = s + b_res[32];
    }
}

// ---------------------------------------------------------------------------
extern "C" void kernel_launch(void* const* d_in, const int* in_sizes, int n_in,
                              void* d_out, int out_size)
{
    const float* a      = (const float*)d_in[0];
    const float* q      = (const float*)d_in[1];
    // d_in[2] = c            (unused by reference)
    const int*   tok    = (const int*)  d_in[3];
    // d_in[4] = atom_to_token one-hot (replaced by gather via tok)
    // d_in[5] = atom_pad_mask (all ones by construction)
    const float* W_a2q  = (const float*)d_in[6];
    const float* gamma  = (const float*)d_in[7];
    const float* beta   = (const float*)d_in[8];
    const float* W_pos  = (const float*)d_in[9];
    const float* W_res  = (const float*)d_in[10];
    const float* b_res  = (const float*)d_in[11];
    const float* W_atom = (const float*)d_in[12];
    const float* b_atom = (const float*)d_in[13];
    const int*   allowed= (const int*)  d_in[14];

    float* out     = (float*)d_out;
    float* out_r   = out;                                   // [B,NA,3]
    float* out_res = out + (size_t)BB*NA*3;                 // [B,NT,33]
    float* out_at  = out_res + (size_t)BB*NT*33;            // [B,NA,128]

    k0_prep <<<48, 256>>>(W_a2q);
    k1_gemm <<<BT_TOT/16, 256>>>(a);
    k2_atoms<<<GA_TOT/32, 256>>>(q, tok, W_atom, b_atom, allowed,
                                 gamma, beta, W_pos, out_r, out_at);
    k3_res  <<<BT_TOT/8, 256>>>(W_res, b_res, out_res);
}

// round 10
// speedup vs baseline: 1.3362x; 1.0293x over previous
#include <cuda_runtime.h>

#define BB 4
#define NT 1024
#define NA 8192
#define DD 128
#define SS 384
#define GA_TOT (BB*NA)     // 32768 atoms
#define BT_TOT (BB*NT)     // 4096 tokens
#define PAD_VALF (-1e9f)

// scratch (no allocs allowed)
__device__ float g_a2q[BT_TOT*DD];     // [B,T,128]  2 MB
__device__ float g_sfeat[BT_TOT*DD];   // [B,T,128]  2 MB
__device__ float g_Wt[SS*DD];          // W_a2q transposed [s][d]

// ---------------------------------------------------------------------------
// k0: transpose W_a2q [128][384] -> g_Wt [384][128] (blocks 0..47)
//     + zero g_sfeat (all 192 blocks)
// ---------------------------------------------------------------------------
__global__ void k0_prep(const float* __restrict__ W)
{
    const int tid = threadIdx.x;

    int gt = blockIdx.x * 256 + tid;
    for (int i = gt; i < BT_TOT*DD/4; i += 192*256)
        ((float4*)g_sfeat)[i] = make_float4(0.f, 0.f, 0.f, 0.f);

    if (blockIdx.x < 48) {
        __shared__ float t[32][33];
        const int x  = tid & 31;
        const int y8 = tid >> 5;                  // 0..7
        const int td = (blockIdx.x & 3)  * 32;    // d tile
        const int ts = (blockIdx.x >> 2) * 32;    // s tile
#pragma unroll
        for (int j = 0; j < 32; j += 8)
            t[y8 + j][x] = W[(td + y8 + j)*SS + ts + x];
        __syncthreads();
#pragma unroll
        for (int j = 0; j < 32; j += 8)
            g_Wt[(ts + y8 + j)*DD + td + x] = t[x][y8 + j];
    }
}

// ---------------------------------------------------------------------------
// k1: a_to_q = a[4096x384] @ Wt[384x128]
// tile: 16 tokens x 128 d, 256 threads, thread = 2 tok x 4 d. grid 256.
// ---------------------------------------------------------------------------
__global__ void __launch_bounds__(256) k1_gemm(const float* __restrict__ a)
{
    __shared__ float a_s[16][64];     // 4 KB
    __shared__ float w_s[64][128];    // 32 KB

    const int tid = threadIdx.x;
    const int bt0 = blockIdx.x * 16;
    const int dq  = tid & 31;         // d-quad (d = dq*4)
    const int tg  = tid >> 5;         // 0..7 -> tokens tg*2, tg*2+1

    float acc[2][4];
#pragma unroll
    for (int t = 0; t < 2; t++)
#pragma unroll
        for (int j = 0; j < 4; j++) acc[t][j] = 0.f;

    for (int sc = 0; sc < SS; sc += 64) {
        {
            int t = tid >> 4, c = tid & 15;
            *(float4*)&a_s[t][c*4] =
                *(const float4*)(a + (size_t)(bt0 + t)*SS + sc + c*4);
        }
        {
            const float4* wsrc = (const float4*)(g_Wt + sc*DD);
            float4* wdst = (float4*)w_s;
#pragma unroll
            for (int j = 0; j < 8; j++)
                wdst[tid + j*256] = wsrc[tid + j*256];
        }
        __syncthreads();

#pragma unroll
        for (int s = 0; s < 64; s += 4) {
            float4 w0 = *(float4*)&w_s[s+0][dq*4];
            float4 w1 = *(float4*)&w_s[s+1][dq*4];
            float4 w2 = *(float4*)&w_s[s+2][dq*4];
            float4 w3 = *(float4*)&w_s[s+3][dq*4];
#pragma unroll
            for (int t = 0; t < 2; t++) {
                float4 av = *(float4*)&a_s[tg*2 + t][s];
                acc[t][0] = fmaf(av.x, w0.x, fmaf(av.y, w1.x,
                            fmaf(av.z, w2.x, fmaf(av.w, w3.x, acc[t][0]))));
                acc[t][1] = fmaf(av.x, w0.y, fmaf(av.y, w1.y,
                            fmaf(av.z, w2.y, fmaf(av.w, w3.y, acc[t][1]))));
                acc[t][2] = fmaf(av.x, w0.z, fmaf(av.y, w1.z,
                            fmaf(av.z, w2.z, fmaf(av.w, w3.z, acc[t][2]))));
                acc[t][3] = fmaf(av.x, w0.w, fmaf(av.y, w1.w,
                            fmaf(av.z, w2.w, fmaf(av.w, w3.w, acc[t][3]))));
            }
        }
        __syncthreads();
    }
#pragma unroll
    for (int t = 0; t < 2; t++) {
        float4 v = make_float4(acc[t][0], acc[t][1], acc[t][2], acc[t][3]);
        *(float4*)(g_a2q + (size_t)(bt0 + tg*2 + t)*DD + dq*4) = v;
    }
}

// ---------------------------------------------------------------------------
// k2: per-atom fused stage (32 atoms / block, 256 threads, grid 1024)
//   qn = q + a_to_q[tok]            (gather)
//   s_feat[tok] += qn               (run-length aggregated atomics)
//   atom_type: logits -> lg smem; out_at emitted directly via inverse map
//   r_update : LayerNorm(qn) @ W_pos^T
// ---------------------------------------------------------------------------
__global__ void __launch_bounds__(256) k2_atoms(
                         const float* __restrict__ q,
                         const int*   __restrict__ tok,
                         const float* __restrict__ W_atom,
                         const float* __restrict__ b_atom,
                         const int*   __restrict__ allowed,
                         const float* __restrict__ gamma,
                         const float* __restrict__ beta,
                         const float* __restrict__ W_pos,
                         float* __restrict__ out_r,
                         float* __restrict__ out_at)
{
    __shared__ float sh_q[32][DD];       // 16 KB
    __shared__ float sh_wt[DD*33];       // 16.9 KB: W_atom^T [d*33+k]
    __shared__ float lg[32*33];          // 4.2 KB atom logits [ia*33+k]
    __shared__ float sh_pos[3][DD];
    __shared__ float sh_g[DD], sh_b[DD];
    __shared__ float sh_batom[32];
    __shared__ int   sh_tok[32];
    __shared__ int   sh_allowed[32];
    __shared__ int   sh_inv[DD];         // col -> k (or -1)

    const int tid   = threadIdx.x;
    const int atom0 = blockIdx.x * 32;
    const int b     = atom0 >> 13;          // atom0 / 8192

    if (tid < 32) {
        sh_tok[tid]     = tok[atom0 + tid];
        sh_batom[tid]   = b_atom[tid];
        sh_allowed[tid] = allowed[tid];
    }
    if (tid < DD) {
        sh_g[tid] = gamma[tid]; sh_b[tid] = beta[tid];
        sh_inv[tid] = -1;
    }
    for (int i = tid; i < 32*DD; i += 256)          // W_atom is [k][d]
        sh_wt[(i & 127)*33 + (i >> 7)] = W_atom[i]; // pitch 33: conflict-free
    for (int i = tid; i < 3*DD; i += 256)
        sh_pos[i >> 7][i & 127] = W_pos[i];
    __syncthreads();

    if (tid < 32) sh_inv[sh_allowed[tid]] = tid;    // visible after next sync

    // ---- gather (coalesced float4) ----
    for (int i = tid; i < 32*(DD/4); i += 256) {
        int ia = i >> 5, d4 = i & 31;
        int ga = atom0 + ia;
        int t  = sh_tok[ia];
        float4 qv = ((const float4*)q)[(size_t)ga*(DD/4) + d4];
        float4 av = ((const float4*)g_a2q)[(size_t)(b*NT + t)*(DD/4) + d4];
        *(float4*)&sh_q[ia][d4*4] =
            make_float4(qv.x+av.x, qv.y+av.y, qv.z+av.z, qv.w+av.w);
    }
    __syncthreads();

    // ---- scatter-add, run-length aggregated (tok sorted => ~4 runs/block) ----
    {
        int d    = tid & 127;
        int i0   = (tid >> 7) * 16;
        int cur  = sh_tok[i0];
        float run = 0.f;
#pragma unroll
        for (int i = 0; i < 16; i++) {
            int t = sh_tok[i0 + i];
            if (t != cur) {
                atomicAdd(&g_sfeat[(size_t)(b*NT + cur)*DD + d], run);
                run = 0.f; cur = t;
            }
            run += sh_q[i0 + i][d];
        }
        atomicAdd(&g_sfeat[(size_t)(b*NT + cur)*DD + d], run);
    }

    // ---- atom-type head: thread (ig,k) owns logit k for 4 atoms ----
    const int k   = tid & 31;
    const int ig  = tid >> 5;          // warp id, 0..7
    const int ia0 = ig * 4;
    float acc0 = sh_batom[k], acc1 = acc0, acc2 = acc0, acc3 = acc0;
#pragma unroll 8
    for (int d = 0; d < DD; d += 4) {
        float w0 = sh_wt[(d+0)*33 + k], w1 = sh_wt[(d+1)*33 + k];
        float w2 = sh_wt[(d+2)*33 + k], w3 = sh_wt[(d+3)*33 + k];
        float4 q0 = *(const float4*)&sh_q[ia0+0][d];
        float4 q1 = *(const float4*)&sh_q[ia0+1][d];
        float4 q2 = *(const float4*)&sh_q[ia0+2][d];
        float4 q3 = *(const float4*)&sh_q[ia0+3][d];
        acc0 += q0.x*w0 + q0.y*w1 + q0.z*w2 + q0.w*w3;
        acc1 += q1.x*w0 + q1.y*w1 + q1.z*w2 + q1.w*w3;
        acc2 += q2.x*w0 + q2.y*w1 + q2.z*w2 + q2.w*w3;
        acc3 += q3.x*w0 + q3.y*w1 + q3.z*w2 + q3.w*w3;
    }
    lg[(ia0+0)*33 + k] = acc0;
    lg[(ia0+1)*33 + k] = acc1;
    lg[(ia0+2)*33 + k] = acc2;
    lg[(ia0+3)*33 + k] = acc3;
    __syncthreads();

    // ---- out_at: direct float4 emit via inverse map ----
    for (int i = tid; i < 32*(DD/4); i += 256) {
        int ia = i >> 5, d4 = i & 31;
        int c0 = d4 * 4;
        int k0 = sh_inv[c0+0], k1 = sh_inv[c0+1];
        int k2 = sh_inv[c0+2], k3 = sh_inv[c0+3];
        float4 v;
        v.x = (k0 >= 0) ? lg[ia*33 + k0] : PAD_VALF;
        v.y = (k1 >= 0) ? lg[ia*33 + k1] : PAD_VALF;
        v.z = (k2 >= 0) ? lg[ia*33 + k2] : PAD_VALF;
        v.w = (k3 >= 0) ? lg[ia*33 + k3] : PAD_VALF;
        ((float4*)out_at)[(size_t)(atom0 + ia)*(DD/4) + d4] = v;
    }

    // ---- LayerNorm + pos head: warp ig handles atoms ia0..ia0+3 ----
    const int lane  = k;
    const int dbase = lane * 4;
    for (int r = 0; r < 4; r++) {
        int ia = ia0 + r;
        float4 v = *(const float4*)&sh_q[ia][dbase];
        float s = v.x + v.y + v.z + v.w;
#pragma unroll
        for (int o = 16; o > 0; o >>= 1) s += __shfl_xor_sync(0xffffffffu, s, o);
        float mu = s * (1.f/128.f);
        float d0 = v.x-mu, d1 = v.y-mu, d2 = v.z-mu, d3 = v.w-mu;
        float sq = d0*d0 + d1*d1 + d2*d2 + d3*d3;
#pragma unroll
        for (int o = 16; o > 0; o >>= 1) sq += __shfl_xor_sync(0xffffffffu, sq, o);
        float inv = rsqrtf(sq * (1.f/128.f) + 1e-5f);
        float n0 = d0*inv*sh_g[dbase+0] + sh_b[dbase+0];
        float n1 = d1*inv*sh_g[dbase+1] + sh_b[dbase+1];
        float n2 = d2*inv*sh_g[dbase+2] + sh_b[dbase+2];
        float n3 = d3*inv*sh_g[dbase+3] + sh_b[dbase+3];
        float p0 = n0*sh_pos[0][dbase+0] + n1*sh_pos[0][dbase+1]
                 + n2*sh_pos[0][dbase+2] + n3*sh_pos[0][dbase+3];
        float p1 = n0*sh_pos[1][dbase+0] + n1*sh_pos[1][dbase+1]
                 + n2*sh_pos[1][dbase+2] + n3*sh_pos[1][dbase+3];
        float p2 = n0*sh_pos[2][dbase+0] + n1*sh_pos[2][dbase+1]
                 + n2*sh_pos[2][dbase+2] + n3*sh_pos[2][dbase+3];
#pragma unroll
        for (int o = 16; o > 0; o >>= 1) {
            p0 += __shfl_xor_sync(0xffffffffu, p0, o);
            p1 += __shfl_xor_sync(0xffffffffu, p1, o);
            p2 += __shfl_xor_sync(0xffffffffu, p2, o);
        }
        if (lane == 0) {
            size_t ro = (size_t)(atom0 + ia) * 3;
            out_r[ro+0] = p0; out_r[ro+1] = p1; out_r[ro+2] = p2;
        }
    }
}

// ---------------------------------------------------------------------------
// k3: res_type[bt,k] = s_feat[bt,:] . W_res[k,:] + b_res[k]
// 256 blocks x 256 threads; 16 tokens/block; warp = 2 tokens, lane = k.
// W_res staged [k][132] -> per-lane LDS.128, conflict-free per quarter-warp.
// ---------------------------------------------------------------------------
__global__ void __launch_bounds__(256) k3_res(const float* __restrict__ W_res,
                                              const float* __restrict__ b_res,
                                              float* __restrict__ out_res)
{
    __shared__ float shW[33*132];    // 17.4 KB: [k][132]
    __shared__ float shF[16*DD];     // 8 KB

    const int tid = threadIdx.x;
    const int bt0 = blockIdx.x * 16;

    for (int i = tid; i < 33*DD; i += 256)          // i = k*128 + d
        shW[(i >> 7)*132 + (i & 127)] = W_res[i];
    {
        const float4* src = (const float4*)(g_sfeat + (size_t)bt0*DD);
        ((float4*)shF)[tid]       = src[tid];
        ((float4*)shF)[tid + 256] = src[tid + 256];
    }
    __syncthreads();

    const int lane = tid & 31;                      // k
    const int w    = tid >> 5;                      // 0..7
    const int t0   = w * 2;
    const float* f0p = &shF[t0*DD];
    const float* f1p = &shF[(t0+1)*DD];

    float acc0 = b_res[lane];
    float acc1 = acc0;
#pragma unroll 16
    for (int d = 0; d < DD; d += 4) {
        float4 wv = *(const float4*)&shW[lane*132 + d];
        float4 f0 = *(const float4*)(f0p + d);
        float4 f1 = *(const float4*)(f1p + d);
        acc0 = fmaf(f0.x, wv.x, fmaf(f0.y, wv.y,
               fmaf(f0.z, wv.z, fmaf(f0.w, wv.w, acc0))));
        acc1 = fmaf(f1.x, wv.x, fmaf(f1.y, wv.y,
               fmaf(f1.z, wv.z, fmaf(f1.w, wv.w, acc1))));
    }
    out_res[(size_t)(bt0 + t0)*33 + lane]     = acc0;
    out_res[(size_t)(bt0 + t0 + 1)*33 + lane] = acc1;

    // k = 32: lane-parallel partial dots + shuffle reduce (both tokens)
    {
        const int dbase = lane * 4;
        float4 wv = *(const float4*)&shW[32*132 + dbase];
        float4 a0 = *(const float4*)(f0p + dbase);
        float4 a1 = *(const float4*)(f1p + dbase);
        float s0 = a0.x*wv.x + a0.y*wv.y + a0.z*wv.z + a0.w*wv.w;
        float s1 = a1.x*wv.x + a1.y*wv.y + a1.z*wv.z + a1.w*wv.w;
#pragma unroll
        for (int o = 16; o > 0; o >>= 1) {
            s0 += __shfl_xor_sync(0xffffffffu, s0, o);
            s1 += __shfl_xor_sync(0xffffffffu, s1, o);
        }
        if (lane == 0) {
            float b32 = b_res[32];
            out_res[(size_t)(bt0 + t0)*33 + 32]     = s0 + b32;
            out_res[(size_t)(bt0 + t0 + 1)*33 + 32] = s1 + b32;
        }
    }
}

// ---------------------------------------------------------------------------
extern "C" void kernel_launch(void* const* d_in, const int* in_sizes, int n_in,
                              void* d_out, int out_size)
{
    const float* a      = (const float*)d_in[0];
    const float* q      = (const float*)d_in[1];
    // d_in[2] = c            (unused by reference)
    const int*   tok    = (const int*)  d_in[3];
    // d_in[4] = atom_to_token one-hot (replaced by gather via tok)
    // d_in[5] = atom_pad_mask (all ones by construction)
    const float* W_a2q  = (const float*)d_in[6];
    const float* gamma  = (const float*)d_in[7];
    const float* beta   = (const float*)d_in[8];
    const float* W_pos  = (const float*)d_in[9];
    const float* W_res  = (const float*)d_in[10];
    const float* b_res  = (const float*)d_in[11];
    const float* W_atom = (const float*)d_in[12];
    const float* b_atom = (const float*)d_in[13];
    const int*   allowed= (const int*)  d_in[14];

    float* out     = (float*)d_out;
    float* out_r   = out;                                   // [B,NA,3]
    float* out_res = out + (size_t)BB*NA*3;                 // [B,NT,33]
    float* out_at  = out_res + (size_t)BB*NT*33;            // [B,NA,128]

    k0_prep <<<192, 256>>>(W_a2q);
    k1_gemm <<<BT_TOT/16, 256>>>(a);
    k2_atoms<<<GA_TOT/32, 256>>>(q, tok, W_atom, b_atom, allowed,
                                 gamma, beta, W_pos, out_r, out_at);
    k3_res  <<<BT_TOT/16, 256>>>(W_res, b_res, out_res);
}